// round 3
// baseline (speedup 1.0000x reference)
#include <cuda_runtime.h>

#define DIM     128
#define NMAX    100000
#define MAXDEG  128
#define GPAD    132   // smem row pad (floats): 16B-aligned float4 rows, conflict-free

// Scratch (allocation-free rule: module-scope device arrays)
__device__ int   g_deg[NMAX];
__device__ int   g_bucket[(size_t)NMAX * MAXDEG];   // 51.2 MB
__device__ float g_y[(size_t)NMAX * DIM];           // 51.2 MB
__device__ float g_beta[NMAX];

// ---------------------------------------------------------------------------
// K0: zero degrees
// ---------------------------------------------------------------------------
__global__ void zero_deg_kernel(int n) {
    int i = blockIdx.x * blockDim.x + threadIdx.x;
    if (i < n) g_deg[i] = 0;
}

// ---------------------------------------------------------------------------
// K1: count degrees + scatter neighbor lists into fixed-stride buckets.
// edge_index arrives as int32 (harness converts int64 inputs to int32).
// Bounds-guarded: a bad index degrades accuracy, never faults.
// ---------------------------------------------------------------------------
__global__ void fill_kernel(const int* __restrict__ ei, int e, int n) {
    int i = blockIdx.x * blockDim.x + threadIdx.x;
    if (i >= e) return;
    int row = ei[i];
    int col = ei[(size_t)e + i];
    if ((unsigned)row >= (unsigned)n) return;
    if ((unsigned)col >= (unsigned)n) return;
    int slot = atomicAdd(&g_deg[row], 1);
    if (slot < MAXDEG) g_bucket[(size_t)row * MAXDEG + slot] = col;
}

// ---------------------------------------------------------------------------
// K2: per-row aggregation in x-space.
// y[r] = d_r * sum_c d_c * x[c]  +  d_r^2 * x[r]
// beta[r] = d_r * sum_c d_c + d_r^2
// One warp per row; each lane owns a float4 (4 of 128 cols).
// ---------------------------------------------------------------------------
__global__ void agg_kernel(const float* __restrict__ x, int n) {
    int gw   = (blockIdx.x * blockDim.x + threadIdx.x) >> 5;
    int lane = threadIdx.x & 31;
    if (gw >= n) return;

    int degr = g_deg[gw];
    int degc = min(degr, MAXDEG);      // bucket holds at most MAXDEG entries
    const float4* __restrict__ x4 = (const float4*)x;

    float4 acc = make_float4(0.f, 0.f, 0.f, 0.f);
    float  s   = 0.f;

    for (int base = 0; base < degc; base += 32) {
        int m = min(32, degc - base);
        int   c  = 0;
        float dc = 0.f;
        if (lane < m) {
            c  = g_bucket[(size_t)gw * MAXDEG + base + lane];
            dc = rsqrtf((float)max(g_deg[c], 1));
        }
#pragma unroll 4
        for (int j = 0; j < m; j++) {
            int   cj  = __shfl_sync(0xffffffffu, c, j);
            float dcj = __shfl_sync(0xffffffffu, dc, j);
            float4 v  = x4[(size_t)cj * (DIM / 4) + lane];
            acc.x += dcj * v.x;
            acc.y += dcj * v.y;
            acc.z += dcj * v.z;
            acc.w += dcj * v.w;
            s += dcj;
        }
    }

    float dr = rsqrtf((float)max(degr, 1));
    float d2 = dr * dr;
    float4 xr = x4[(size_t)gw * (DIM / 4) + lane];
    float4 yv;
    yv.x = dr * acc.x + d2 * xr.x;
    yv.y = dr * acc.y + d2 * xr.y;
    yv.z = dr * acc.z + d2 * xr.z;
    yv.w = dr * acc.w + d2 * xr.w;
    ((float4*)g_y)[(size_t)gw * (DIM / 4) + lane] = yv;

    if (lane == 0) g_beta[gw] = dr * s + d2;
}

// ---------------------------------------------------------------------------
// K3: out[r] = y[r] @ W^T + beta[r] * b
// W^T staged in STATIC smem in two K-phases (64 k-rows each, 33.8 KB).
// Block = 256 threads; warp -> 8 rows; thread -> 8 rows x 4 cols register tile.
// y read via LDG broadcast (all lanes same address -> 1 sector).
// ---------------------------------------------------------------------------
__global__ void gemm_kernel(const float* __restrict__ W,
                            const float* __restrict__ bvec,
                            float* __restrict__ out, int n) {
    __shared__ float Wt[64][GPAD];   // [k within phase][o], 33792 B

    int lane = threadIdx.x & 31;
    int warp = threadIdx.x >> 5;
    int o0   = lane * 4;
    int row0 = blockIdx.x * 64 + warp * 8;

    float acc[8][4];
    float4 bv = *(const float4*)(bvec + o0);
#pragma unroll
    for (int i = 0; i < 8; i++) {
        int r = row0 + i;
        float be = (r < n) ? g_beta[r] : 0.f;
        acc[i][0] = be * bv.x;
        acc[i][1] = be * bv.y;
        acc[i][2] = be * bv.z;
        acc[i][3] = be * bv.w;
    }

    const float* __restrict__ yb = g_y + (size_t)row0 * DIM;
    int rm = n - row0;   // rows valid in this block's warp tile (may exceed 8)

    for (int phase = 0; phase < 2; phase++) {
        int k0 = phase * 64;
        __syncthreads();
        for (int i = threadIdx.x; i < DIM * 64; i += 256) {
            int o = i >> 6;
            int k = i & 63;
            Wt[k][o] = W[o * DIM + k0 + k];
        }
        __syncthreads();

        if (rm >= 8) {
#pragma unroll 4
            for (int k = 0; k < 64; k++) {
                float4 w = *(const float4*)(&Wt[k][o0]);
#pragma unroll
                for (int i = 0; i < 8; i++) {
                    float yv = yb[(size_t)i * DIM + k0 + k];
                    acc[i][0] += yv * w.x;
                    acc[i][1] += yv * w.y;
                    acc[i][2] += yv * w.z;
                    acc[i][3] += yv * w.w;
                }
            }
        } else if (rm > 0) {
            for (int k = 0; k < 64; k++) {
                float4 w = *(const float4*)(&Wt[k][o0]);
                for (int i = 0; i < 8; i++) {
                    if (i < rm) {
                        float yv = yb[(size_t)i * DIM + k0 + k];
                        acc[i][0] += yv * w.x;
                        acc[i][1] += yv * w.y;
                        acc[i][2] += yv * w.z;
                        acc[i][3] += yv * w.w;
                    }
                }
            }
        }
    }

#pragma unroll
    for (int i = 0; i < 8; i++) {
        int r = row0 + i;
        if (r < n) {
            *((float4*)(out + (size_t)r * DIM + o0)) =
                make_float4(acc[i][0], acc[i][1], acc[i][2], acc[i][3]);
        }
    }
}

// ---------------------------------------------------------------------------
// Launch
// ---------------------------------------------------------------------------
extern "C" void kernel_launch(void* const* d_in, const int* in_sizes, int n_in,
                              void* d_out, int out_size) {
    const float* x   = (const float*)d_in[0];
    const int*   ei  = (const int*)d_in[1];     // int64 inputs delivered as int32
    const float* W   = (const float*)d_in[2];
    const float* b   = (const float*)d_in[3];
    float*       out = (float*)d_out;

    int n = in_sizes[0] / DIM;
    int e = in_sizes[1] / 2;

    zero_deg_kernel<<<(n + 255) / 256, 256>>>(n);
    fill_kernel<<<(e + 255) / 256, 256>>>(ei, e, n);
    agg_kernel<<<((n * 32) + 255) / 256, 256>>>(x, n);
    gemm_kernel<<<(n + 63) / 64, 256>>>(W, b, out, n);
}

// round 5
// speedup vs baseline: 1.4559x; 1.4559x over previous
#include <cuda_runtime.h>
#include <cuda_fp16.h>
#include <cstdint>

#define DIM     128
#define NMAX    100000
#define MAXDEG  128
#define TILE_M  128

// ---------------------------------------------------------------------------
// Scratch (allocation-free rule: module-scope device arrays)
// ---------------------------------------------------------------------------
__device__ int    g_deg[NMAX];
__device__ int    g_bucket[(size_t)NMAX * MAXDEG];     // 51.2 MB
__device__ __half g_xh[(size_t)NMAX * DIM];            // 25.6 MB  x in fp16
__device__ __half g_yh[(size_t)(NMAX + TILE_M) * DIM]; // fp16 y (padded tail)
__device__ __half g_Wh[DIM * DIM];                     // W in fp16
__device__ float  g_beta[NMAX];

// ---------------------------------------------------------------------------
// K0: zero degrees
// ---------------------------------------------------------------------------
__global__ void zero_deg_kernel(int n) {
    int i = blockIdx.x * blockDim.x + threadIdx.x;
    if (i < n) g_deg[i] = 0;
}

// ---------------------------------------------------------------------------
// K1: convert x -> fp16
// ---------------------------------------------------------------------------
__global__ void conv_x_kernel(const float* __restrict__ x, int n) {
    size_t total = (size_t)n * (DIM / 2);
    size_t i = (size_t)blockIdx.x * blockDim.x + threadIdx.x;
    if (i >= total) return;
    float2 v = ((const float2*)x)[i];
    ((__half2*)g_xh)[i] = __float22half2_rn(v);
}

// ---------------------------------------------------------------------------
// K1b: convert W -> fp16
// ---------------------------------------------------------------------------
__global__ void conv_w_kernel(const float* __restrict__ W) {
    int i = blockIdx.x * blockDim.x + threadIdx.x;   // 8192 half2
    if (i >= DIM * DIM / 2) return;
    float2 v = ((const float2*)W)[i];
    ((__half2*)g_Wh)[i] = __float22half2_rn(v);
}

// ---------------------------------------------------------------------------
// K2: count degrees + scatter neighbor lists (edge_index delivered as int32)
// ---------------------------------------------------------------------------
__global__ void fill_kernel(const int* __restrict__ ei, int e, int n) {
    int i = blockIdx.x * blockDim.x + threadIdx.x;
    if (i >= e) return;
    int row = ei[i];
    int col = ei[(size_t)e + i];
    if ((unsigned)row >= (unsigned)n) return;
    if ((unsigned)col >= (unsigned)n) return;
    int slot = atomicAdd(&g_deg[row], 1);
    if (slot < MAXDEG) g_bucket[(size_t)row * MAXDEG + slot] = col;
}

// ---------------------------------------------------------------------------
// K3: warp-per-row aggregation, fp16 gather, fp32 accumulate, fp16 y out.
// y[r] = d_r * sum_c d_c * x[c] + d_r^2 * x[r];  beta[r] = d_r*sum d_c + d_r^2
// ---------------------------------------------------------------------------
__global__ void agg_kernel(int n) {
    int gw   = (blockIdx.x * blockDim.x + threadIdx.x) >> 5;
    int lane = threadIdx.x & 31;
    if (gw >= n) return;

    int degr = g_deg[gw];
    int degc = min(degr, MAXDEG);

    float a0 = 0.f, a1 = 0.f, a2 = 0.f, a3 = 0.f, s = 0.f;

    for (int base = 0; base < degc; base += 32) {
        int m = min(32, degc - base);
        int   c  = 0;
        float dc = 0.f;
        if (lane < m) {
            c  = g_bucket[(size_t)gw * MAXDEG + base + lane];
            dc = rsqrtf((float)max(g_deg[c], 1));
        }
#pragma unroll 4
        for (int j = 0; j < m; j++) {
            int   cj  = __shfl_sync(0xffffffffu, c, j);
            float dcj = __shfl_sync(0xffffffffu, dc, j);
            uint2 raw = *(const uint2*)(g_xh + (size_t)cj * DIM + lane * 4);
            float2 f01 = __half22float2(*(const __half2*)&raw.x);
            float2 f23 = __half22float2(*(const __half2*)&raw.y);
            a0 += dcj * f01.x;  a1 += dcj * f01.y;
            a2 += dcj * f23.x;  a3 += dcj * f23.y;
            s  += dcj;
        }
    }

    float dr = rsqrtf((float)max(degr, 1));
    float d2 = dr * dr;
    uint2 xraw = *(const uint2*)(g_xh + (size_t)gw * DIM + lane * 4);
    float2 x01 = __half22float2(*(const __half2*)&xraw.x);
    float2 x23 = __half22float2(*(const __half2*)&xraw.y);

    __half2 p0 = __float22half2_rn(make_float2(dr * a0 + d2 * x01.x,
                                               dr * a1 + d2 * x01.y));
    __half2 p1 = __float22half2_rn(make_float2(dr * a2 + d2 * x23.x,
                                               dr * a3 + d2 * x23.y));
    uint2 yv;
    yv.x = *(const uint32_t*)&p0;
    yv.y = *(const uint32_t*)&p1;
    *(uint2*)(g_yh + (size_t)gw * DIM + lane * 4) = yv;

    if (lane == 0) g_beta[gw] = dr * s + d2;
}

// ---------------------------------------------------------------------------
// mma.sync m16n8k16 fp16 -> fp32 (baseline PTX, no 'a' target feature needed)
// ---------------------------------------------------------------------------
__device__ __forceinline__ void mma16816(float c[4],
                                         uint32_t a0, uint32_t a1,
                                         uint32_t a2, uint32_t a3,
                                         uint32_t b0, uint32_t b1) {
    asm volatile(
        "mma.sync.aligned.m16n8k16.row.col.f32.f16.f16.f32 "
        "{%0,%1,%2,%3}, {%4,%5,%6,%7}, {%8,%9}, {%0,%1,%2,%3};"
        : "+f"(c[0]), "+f"(c[1]), "+f"(c[2]), "+f"(c[3])
        : "r"(a0), "r"(a1), "r"(a2), "r"(a3), "r"(b0), "r"(b1));
}

// ---------------------------------------------------------------------------
// K4: HMMA GEMM: out[r] = y[r] @ W^T + beta[r]*b
// Block = 256 thr (8 warps) -> 128 rows x 128 cols. Warp = 32 rows x 64 cols.
// No smem: A fragments straight from g_yh (quad-contiguous 4B loads),
// B fragments straight from g_Wh (W[o][k] row-major == .col B layout,
// 32 KB L1-resident). Epilogue folds beta[r]*b[c].
// ---------------------------------------------------------------------------
__global__ void __launch_bounds__(256)
gemm_mma_kernel(const float* __restrict__ bvec, float* __restrict__ out, int n) {
    int tid   = threadIdx.x;
    int wid   = tid >> 5;
    int lane  = tid & 31;
    int warpM = wid & 3;              // 4 M-slices of 32 rows
    int warpN = wid >> 2;             // 2 N-slices of 64 cols
    int row0  = blockIdx.x * TILE_M + warpM * 32;
    int n0    = warpN * 64;
    int g     = lane >> 2;            // group row/col
    int i2    = (lane & 3) * 2;       // element pair offset

    float c[2][8][4];
#pragma unroll
    for (int mt = 0; mt < 2; mt++)
#pragma unroll
        for (int nt = 0; nt < 8; nt++)
#pragma unroll
            for (int q = 0; q < 4; q++) c[mt][nt][q] = 0.f;

#pragma unroll
    for (int k = 0; k < 8; k++) {
        int kb = k * 16;

        uint32_t a[2][4];
#pragma unroll
        for (int mt = 0; mt < 2; mt++) {
            const __half* base = g_yh + (size_t)(row0 + mt * 16 + g) * DIM + kb + i2;
            a[mt][0] = *(const uint32_t*)(base);
            a[mt][1] = *(const uint32_t*)(base + 8 * DIM);
            a[mt][2] = *(const uint32_t*)(base + 8);
            a[mt][3] = *(const uint32_t*)(base + 8 * DIM + 8);
        }

#pragma unroll
        for (int nt = 0; nt < 8; nt++) {
            int o = n0 + nt * 8 + g;
            const __half* wb = g_Wh + o * DIM + kb + i2;
            uint32_t b0 = *(const uint32_t*)(wb);
            uint32_t b1 = *(const uint32_t*)(wb + 8);
#pragma unroll
            for (int mt = 0; mt < 2; mt++)
                mma16816(c[mt][nt], a[mt][0], a[mt][1], a[mt][2], a[mt][3], b0, b1);
        }
    }

    // Epilogue: c0,c1 -> row g, cols i2,i2+1; c2,c3 -> row g+8.
#pragma unroll
    for (int mt = 0; mt < 2; mt++) {
        int r0 = row0 + mt * 16 + g;
        int r1 = r0 + 8;
        float be0 = (r0 < n) ? g_beta[r0] : 0.f;
        float be1 = (r1 < n) ? g_beta[r1] : 0.f;
#pragma unroll
        for (int nt = 0; nt < 8; nt++) {
            int col = n0 + nt * 8 + i2;
            float2 bv = *(const float2*)(bvec + col);
            if (r0 < n) {
                float2 o0 = make_float2(c[mt][nt][0] + be0 * bv.x,
                                        c[mt][nt][1] + be0 * bv.y);
                *(float2*)(out + (size_t)r0 * DIM + col) = o0;
            }
            if (r1 < n) {
                float2 o1 = make_float2(c[mt][nt][2] + be1 * bv.x,
                                        c[mt][nt][3] + be1 * bv.y);
                *(float2*)(out + (size_t)r1 * DIM + col) = o1;
            }
        }
    }
}

// ---------------------------------------------------------------------------
// Launch
// ---------------------------------------------------------------------------
extern "C" void kernel_launch(void* const* d_in, const int* in_sizes, int n_in,
                              void* d_out, int out_size) {
    const float* x   = (const float*)d_in[0];
    const int*   ei  = (const int*)d_in[1];
    const float* W   = (const float*)d_in[2];
    const float* b   = (const float*)d_in[3];
    float*       out = (float*)d_out;

    int n = in_sizes[0] / DIM;
    int e = in_sizes[1] / 2;

    zero_deg_kernel<<<(n + 255) / 256, 256>>>(n);
    fill_kernel<<<(e + 255) / 256, 256>>>(ei, e, n);
    {
        size_t tot = (size_t)n * (DIM / 2);
        conv_x_kernel<<<(int)((tot + 255) / 256), 256>>>(x, n);
    }
    conv_w_kernel<<<(DIM * DIM / 2 + 255) / 256, 256>>>(W);
    agg_kernel<<<((n * 32) + 255) / 256, 256>>>(n);
    gemm_mma_kernel<<<(n + TILE_M - 1) / TILE_M, 256>>>(b, out, n);
}

// round 6
// speedup vs baseline: 1.4952x; 1.0269x over previous
#include <cuda_runtime.h>
#include <cuda_fp16.h>
#include <cstdint>

#define DIM     128
#define NMAX    100000
#define MAXDEG  128
#define TILE_M  128

// ---------------------------------------------------------------------------
// Scratch (allocation-free rule: module-scope device arrays)
// ---------------------------------------------------------------------------
__device__ int    g_deg[NMAX];
__device__ int    g_bucket[(size_t)NMAX * MAXDEG];     // 51.2 MB
__device__ __half g_xh[(size_t)NMAX * DIM];            // 25.6 MB  x in fp16
__device__ __half g_yh[(size_t)(NMAX + TILE_M) * DIM]; // fp16 y (padded tail)
__device__ __half g_Wh[DIM * DIM];                     // W in fp16
__device__ float  g_beta[NMAX];

// ---------------------------------------------------------------------------
// K0: fused init — zero degrees + x->fp16 + W->fp16 (independent jobs, one
// launch; indexed over the largest job: n*64 half2 conversions)
// ---------------------------------------------------------------------------
__global__ void init_kernel(const float* __restrict__ x,
                            const float* __restrict__ W, int n) {
    size_t i = (size_t)blockIdx.x * blockDim.x + threadIdx.x;
    size_t total = (size_t)n * (DIM / 2);
    if (i < total) {
        float2 v = ((const float2*)x)[i];
        ((__half2*)g_xh)[i] = __float22half2_rn(v);
    }
    if (i < (size_t)n) g_deg[i] = 0;
    if (i < DIM * DIM / 2) {
        float2 v = ((const float2*)W)[i];
        ((__half2*)g_Wh)[i] = __float22half2_rn(v);
    }
}

// ---------------------------------------------------------------------------
// K1: count degrees + scatter neighbor lists (edge_index delivered as int32)
// ---------------------------------------------------------------------------
__global__ void fill_kernel(const int* __restrict__ ei, int e, int n) {
    int i = blockIdx.x * blockDim.x + threadIdx.x;
    if (i >= e) return;
    int row = ei[i];
    int col = ei[(size_t)e + i];
    if ((unsigned)row >= (unsigned)n) return;
    if ((unsigned)col >= (unsigned)n) return;
    int slot = atomicAdd(&g_deg[row], 1);
    if (slot < MAXDEG) g_bucket[(size_t)row * MAXDEG + slot] = col;
}

// ---------------------------------------------------------------------------
// K2: warp-per-row aggregation, 2 neighbors per iteration.
// Half-warp per neighbor row; lane loads uint4 = 8 fp16 cols (LDG.128).
// One iteration moves 512B (2 rows) -> 2x row MLP, half the LDG/SHFL issue.
// y[r] = d_r * sum_c d_c * x[c] + d_r^2 * x[r];  beta[r] = d_r*sum d_c + d_r^2
// ---------------------------------------------------------------------------
__global__ void agg_kernel(int n) {
    int gw   = (blockIdx.x * blockDim.x + threadIdx.x) >> 5;
    int lane = threadIdx.x & 31;
    if (gw >= n) return;

    int degr = g_deg[gw];
    int degc = min(degr, MAXDEG);
    int half = lane >> 4;      // which neighbor of the pair
    int li   = lane & 15;      // 8-col chunk owner within the row

    float acc[8];
#pragma unroll
    for (int t = 0; t < 8; t++) acc[t] = 0.f;
    float s = 0.f;

    for (int base = 0; base < degc; base += 32) {
        int m = min(32, degc - base);
        int   c  = 0;
        float dc = 0.f;
        if (lane < m) {
            c  = g_bucket[(size_t)gw * MAXDEG + base + lane];
            dc = rsqrtf((float)max(g_deg[c], 1));
        }
#pragma unroll 4
        for (int j = 0; j < m; j += 2) {
            int idx = j + half;                       // may be == m (odd m):
            int   cj  = __shfl_sync(0xffffffffu, c, idx);   // lane idx>=m holds 0
            float dcj = __shfl_sync(0xffffffffu, dc, idx);
            uint4 v = *(const uint4*)(g_xh + (size_t)cj * DIM + li * 8);
            const __half2* hp = (const __half2*)&v;
#pragma unroll
            for (int t = 0; t < 4; t++) {
                float2 f = __half22float2(hp[t]);
                acc[t * 2 + 0] += dcj * f.x;
                acc[t * 2 + 1] += dcj * f.y;
            }
            s += dcj;
        }
    }

    // combine odd/even halves: lanes 0-15 <- + lanes 16-31
#pragma unroll
    for (int t = 0; t < 8; t++)
        acc[t] += __shfl_down_sync(0xffffffffu, acc[t], 16);
    s += __shfl_down_sync(0xffffffffu, s, 16);

    float dr = rsqrtf((float)max(degr, 1));
    float d2 = dr * dr;

    if (lane < 16) {
        uint4 xv = *(const uint4*)(g_xh + (size_t)gw * DIM + li * 8);
        const __half2* xp = (const __half2*)&xv;
        uint4 yo;
        uint32_t* yw = (uint32_t*)&yo;
#pragma unroll
        for (int t = 0; t < 4; t++) {
            float2 xf = __half22float2(xp[t]);
            __half2 p = __float22half2_rn(
                make_float2(dr * acc[t * 2 + 0] + d2 * xf.x,
                            dr * acc[t * 2 + 1] + d2 * xf.y));
            yw[t] = *(const uint32_t*)&p;
        }
        *(uint4*)(g_yh + (size_t)gw * DIM + li * 8) = yo;
    }
    if (lane == 0) g_beta[gw] = dr * s + d2;
}

// ---------------------------------------------------------------------------
// mma.sync m16n8k16 fp16 -> fp32 (baseline PTX, no 'a' target feature)
// ---------------------------------------------------------------------------
__device__ __forceinline__ void mma16816(float c[4],
                                         uint32_t a0, uint32_t a1,
                                         uint32_t a2, uint32_t a3,
                                         uint32_t b0, uint32_t b1) {
    asm volatile(
        "mma.sync.aligned.m16n8k16.row.col.f32.f16.f16.f32 "
        "{%0,%1,%2,%3}, {%4,%5,%6,%7}, {%8,%9}, {%0,%1,%2,%3};"
        : "+f"(c[0]), "+f"(c[1]), "+f"(c[2]), "+f"(c[3])
        : "r"(a0), "r"(a1), "r"(a2), "r"(a3), "r"(b0), "r"(b1));
}

// ---------------------------------------------------------------------------
// K3: HMMA GEMM: out[r] = y[r] @ W^T + beta[r]*b   (unchanged from R5)
// ---------------------------------------------------------------------------
__global__ void __launch_bounds__(256)
gemm_mma_kernel(const float* __restrict__ bvec, float* __restrict__ out, int n) {
    int tid   = threadIdx.x;
    int wid   = tid >> 5;
    int lane  = tid & 31;
    int warpM = wid & 3;
    int warpN = wid >> 2;
    int row0  = blockIdx.x * TILE_M + warpM * 32;
    int n0    = warpN * 64;
    int g     = lane >> 2;
    int i2    = (lane & 3) * 2;

    float c[2][8][4];
#pragma unroll
    for (int mt = 0; mt < 2; mt++)
#pragma unroll
        for (int nt = 0; nt < 8; nt++)
#pragma unroll
            for (int q = 0; q < 4; q++) c[mt][nt][q] = 0.f;

#pragma unroll
    for (int k = 0; k < 8; k++) {
        int kb = k * 16;

        uint32_t a[2][4];
#pragma unroll
        for (int mt = 0; mt < 2; mt++) {
            const __half* base = g_yh + (size_t)(row0 + mt * 16 + g) * DIM + kb + i2;
            a[mt][0] = *(const uint32_t*)(base);
            a[mt][1] = *(const uint32_t*)(base + 8 * DIM);
            a[mt][2] = *(const uint32_t*)(base + 8);
            a[mt][3] = *(const uint32_t*)(base + 8 * DIM + 8);
        }

#pragma unroll
        for (int nt = 0; nt < 8; nt++) {
            int o = n0 + nt * 8 + g;
            const __half* wb = g_Wh + o * DIM + kb + i2;
            uint32_t b0 = *(const uint32_t*)(wb);
            uint32_t b1 = *(const uint32_t*)(wb + 8);
#pragma unroll
            for (int mt = 0; mt < 2; mt++)
                mma16816(c[mt][nt], a[mt][0], a[mt][1], a[mt][2], a[mt][3], b0, b1);
        }
    }

#pragma unroll
    for (int mt = 0; mt < 2; mt++) {
        int r0 = row0 + mt * 16 + g;
        int r1 = r0 + 8;
        float be0 = (r0 < n) ? g_beta[r0] : 0.f;
        float be1 = (r1 < n) ? g_beta[r1] : 0.f;
#pragma unroll
        for (int nt = 0; nt < 8; nt++) {
            int col = n0 + nt * 8 + i2;
            float2 bv = *(const float2*)(bvec + col);
            if (r0 < n) {
                *(float2*)(out + (size_t)r0 * DIM + col) =
                    make_float2(c[mt][nt][0] + be0 * bv.x,
                                c[mt][nt][1] + be0 * bv.y);
            }
            if (r1 < n) {
                *(float2*)(out + (size_t)r1 * DIM + col) =
                    make_float2(c[mt][nt][2] + be1 * bv.x,
                                c[mt][nt][3] + be1 * bv.y);
            }
        }
    }
}

// ---------------------------------------------------------------------------
// Launch
// ---------------------------------------------------------------------------
extern "C" void kernel_launch(void* const* d_in, const int* in_sizes, int n_in,
                              void* d_out, int out_size) {
    const float* x   = (const float*)d_in[0];
    const int*   ei  = (const int*)d_in[1];
    const float* W   = (const float*)d_in[2];
    const float* b   = (const float*)d_in[3];
    float*       out = (float*)d_out;

    int n = in_sizes[0] / DIM;
    int e = in_sizes[1] / 2;

    size_t init_tot = (size_t)n * (DIM / 2);
    init_kernel<<<(int)((init_tot + 255) / 256), 256>>>(x, W, n);
    fill_kernel<<<(e + 255) / 256, 256>>>(ei, e, n);
    agg_kernel<<<((n * 32) + 255) / 256, 256>>>(n);
    gemm_mma_kernel<<<(n + TILE_M - 1) / TILE_M, 256>>>(b, out, n);
}

// round 7
// speedup vs baseline: 1.7942x; 1.2000x over previous
#include <cuda_runtime.h>
#include <cuda_fp16.h>
#include <cstdint>

#define DIM     128
#define NMAX    100000
#define MAXDEG  128
#define TILE_M  128
#define SPAD    72          // smem row stride in halfs (64 data + 8 pad = 144B)

// ---------------------------------------------------------------------------
// Scratch (allocation-free rule: module-scope device arrays)
// ---------------------------------------------------------------------------
__device__ int    g_deg[NMAX];
__device__ int    g_bucket[(size_t)NMAX * MAXDEG];     // 51.2 MB
__device__ __half g_xh[(size_t)NMAX * DIM];            // 25.6 MB  x in fp16
__device__ __half g_yh[(size_t)(NMAX + TILE_M) * DIM]; // fp16 y (zero pad tail)
__device__ __half g_Wh[DIM * DIM];                     // W in fp16
__device__ float  g_beta[NMAX];

__device__ __forceinline__ uint32_t smem_u32(const void* p) {
    uint32_t a;
    asm("{ .reg .u64 t; cvta.to.shared.u64 t, %1; cvt.u32.u64 %0, t; }"
        : "=r"(a) : "l"(p));
    return a;
}

// ---------------------------------------------------------------------------
// K0: fused init — zero degrees + x->fp16 + W->fp16
// ---------------------------------------------------------------------------
__global__ void init_kernel(const float* __restrict__ x,
                            const float* __restrict__ W, int n) {
    size_t i = (size_t)blockIdx.x * blockDim.x + threadIdx.x;
    size_t total = (size_t)n * (DIM / 2);
    if (i < total) {
        float2 v = ((const float2*)x)[i];
        ((__half2*)g_xh)[i] = __float22half2_rn(v);
    }
    if (i < (size_t)n) g_deg[i] = 0;
    if (i < DIM * DIM / 2) {
        float2 v = ((const float2*)W)[i];
        ((__half2*)g_Wh)[i] = __float22half2_rn(v);
    }
}

// ---------------------------------------------------------------------------
// K1: count degrees + scatter neighbor lists (edge_index delivered as int32)
// ---------------------------------------------------------------------------
__global__ void fill_kernel(const int* __restrict__ ei, int e, int n) {
    int i = blockIdx.x * blockDim.x + threadIdx.x;
    if (i >= e) return;
    int row = ei[i];
    int col = ei[(size_t)e + i];
    if ((unsigned)row >= (unsigned)n) return;
    if ((unsigned)col >= (unsigned)n) return;
    int slot = atomicAdd(&g_deg[row], 1);
    if (slot < MAXDEG) g_bucket[(size_t)row * MAXDEG + slot] = col;
}

// ---------------------------------------------------------------------------
// K2: warp-per-row aggregation (unchanged from R6)
// ---------------------------------------------------------------------------
__global__ void agg_kernel(int n) {
    int gw   = (blockIdx.x * blockDim.x + threadIdx.x) >> 5;
    int lane = threadIdx.x & 31;
    if (gw >= n) return;

    int degr = g_deg[gw];
    int degc = min(degr, MAXDEG);
    int half = lane >> 4;
    int li   = lane & 15;

    float acc[8];
#pragma unroll
    for (int t = 0; t < 8; t++) acc[t] = 0.f;
    float s = 0.f;

    for (int base = 0; base < degc; base += 32) {
        int m = min(32, degc - base);
        int   c  = 0;
        float dc = 0.f;
        if (lane < m) {
            c  = g_bucket[(size_t)gw * MAXDEG + base + lane];
            dc = rsqrtf((float)max(g_deg[c], 1));
        }
#pragma unroll 4
        for (int j = 0; j < m; j += 2) {
            int idx = j + half;
            int   cj  = __shfl_sync(0xffffffffu, c, idx);
            float dcj = __shfl_sync(0xffffffffu, dc, idx);
            uint4 v = *(const uint4*)(g_xh + (size_t)cj * DIM + li * 8);
            const __half2* hp = (const __half2*)&v;
#pragma unroll
            for (int t = 0; t < 4; t++) {
                float2 f = __half22float2(hp[t]);
                acc[t * 2 + 0] += dcj * f.x;
                acc[t * 2 + 1] += dcj * f.y;
            }
            s += dcj;
        }
    }

#pragma unroll
    for (int t = 0; t < 8; t++)
        acc[t] += __shfl_down_sync(0xffffffffu, acc[t], 16);
    s += __shfl_down_sync(0xffffffffu, s, 16);

    float dr = rsqrtf((float)max(degr, 1));
    float d2 = dr * dr;

    if (lane < 16) {
        uint4 xv = *(const uint4*)(g_xh + (size_t)gw * DIM + li * 8);
        const __half2* xp = (const __half2*)&xv;
        uint4 yo;
        uint32_t* yw = (uint32_t*)&yo;
#pragma unroll
        for (int t = 0; t < 4; t++) {
            float2 xf = __half22float2(xp[t]);
            __half2 p = __float22half2_rn(
                make_float2(dr * acc[t * 2 + 0] + d2 * xf.x,
                            dr * acc[t * 2 + 1] + d2 * xf.y));
            yw[t] = *(const uint32_t*)&p;
        }
        *(uint4*)(g_yh + (size_t)gw * DIM + li * 8) = yo;
    }
    if (lane == 0) g_beta[gw] = dr * s + d2;
}

// ---------------------------------------------------------------------------
// mma.sync m16n8k16 fp16 -> fp32
// ---------------------------------------------------------------------------
__device__ __forceinline__ void mma16816(float c[4],
                                         uint32_t a0, uint32_t a1,
                                         uint32_t a2, uint32_t a3,
                                         uint32_t b0, uint32_t b1) {
    asm volatile(
        "mma.sync.aligned.m16n8k16.row.col.f32.f16.f16.f32 "
        "{%0,%1,%2,%3}, {%4,%5,%6,%7}, {%8,%9}, {%0,%1,%2,%3};"
        : "+f"(c[0]), "+f"(c[1]), "+f"(c[2]), "+f"(c[3])
        : "r"(a0), "r"(a1), "r"(a2), "r"(a3), "r"(b0), "r"(b1));
}

__device__ __forceinline__ void ldsm_x4(uint32_t r[4], uint32_t addr) {
    asm volatile(
        "ldmatrix.sync.aligned.m8n8.x4.shared.b16 {%0,%1,%2,%3}, [%4];"
        : "=r"(r[0]), "=r"(r[1]), "=r"(r[2]), "=r"(r[3]) : "r"(addr));
}

// ---------------------------------------------------------------------------
// K3: HMMA GEMM via smem + ldmatrix: out[r] = y[r] @ W^T + beta[r]*b
// Block = 256 thr (8 warps) -> 128 rows x 128 cols; warp = 32 rows x 64 cols.
// Two k-phases of 64: W half + y half staged in smem ([128][72] halfs each,
// 144B stride -> conflict-free LDSM). Per k-step per warp: 2 A-LDSM.x4 +
// 4 B-LDSM.x4 + 16 HMMA.
// ---------------------------------------------------------------------------
__global__ void __launch_bounds__(256)
gemm_mma_kernel(const float* __restrict__ bvec, float* __restrict__ out, int n) {
    __shared__ __half Wsm[DIM * SPAD];   // 18432 B
    __shared__ __half Ysm[DIM * SPAD];   // 18432 B

    int tid   = threadIdx.x;
    int wid   = tid >> 5;
    int lane  = tid & 31;
    int warpM = wid & 3;               // 4 M-slices of 32 rows
    int warpN = wid >> 2;              // 2 N-slices of 64 cols
    int row0  = blockIdx.x * TILE_M;
    int g     = lane >> 2;
    int i2    = (lane & 3) * 2;

    // LDSM per-lane address components (same formula for A and B tiles):
    // grp 0: rows +0..7  cols +0 | grp1: rows +8..15 cols +0
    // grp 2: rows +0..7  cols +8 | grp3: rows +8..15 cols +8
    int grp = lane >> 3;
    int lr  = lane & 7;
    int ro  = (grp & 1) * 8 + lr;
    int co  = (grp >> 1) * 8;

    uint32_t ybase = smem_u32(Ysm);
    uint32_t wbase = smem_u32(Wsm);

    float c[2][8][4];
#pragma unroll
    for (int mt = 0; mt < 2; mt++)
#pragma unroll
        for (int nt = 0; nt < 8; nt++)
#pragma unroll
            for (int q = 0; q < 4; q++) c[mt][nt][q] = 0.f;

#pragma unroll
    for (int p = 0; p < 2; p++) {
        int kb0 = p * 64;
        __syncthreads();
        // Stage W[.][kb0..kb0+64) and y[row0+.][kb0..kb0+64): 1024 uint4 each
#pragma unroll
        for (int it = 0; it < 4; it++) {
            int idx = tid + it * 256;
            int row = idx >> 3;
            int ch  = (idx & 7) * 8;
            *(uint4*)&Wsm[row * SPAD + ch] =
                *(const uint4*)(g_Wh + row * DIM + kb0 + ch);
            *(uint4*)&Ysm[row * SPAD + ch] =
                *(const uint4*)(g_yh + (size_t)(row0 + row) * DIM + kb0 + ch);
        }
        __syncthreads();

#pragma unroll
        for (int k = 0; k < 4; k++) {
            int kc = k * 16 + co;

            uint32_t a[2][4];
#pragma unroll
            for (int mt = 0; mt < 2; mt++) {
                uint32_t addr = ybase +
                    ((warpM * 32 + mt * 16 + ro) * SPAD + kc) * 2;
                ldsm_x4(a[mt], addr);
            }

#pragma unroll
            for (int ntp = 0; ntp < 4; ntp++) {
                uint32_t bfr[4];
                uint32_t addr = wbase +
                    ((warpN * 64 + ntp * 16 + ro) * SPAD + kc) * 2;
                ldsm_x4(bfr, addr);
                // bfr: {b0 of nt=2ntp, b0 of nt=2ntp+1, b1 of nt=2ntp, b1 of nt=2ntp+1}
#pragma unroll
                for (int mt = 0; mt < 2; mt++) {
                    mma16816(c[mt][ntp * 2 + 0], a[mt][0], a[mt][1], a[mt][2], a[mt][3],
                             bfr[0], bfr[2]);
                    mma16816(c[mt][ntp * 2 + 1], a[mt][0], a[mt][1], a[mt][2], a[mt][3],
                             bfr[1], bfr[3]);
                }
            }
        }
    }

    // Epilogue: c0,c1 -> row g cols i2..i2+1; c2,c3 -> row g+8.
    int n0 = warpN * 64;
#pragma unroll
    for (int mt = 0; mt < 2; mt++) {
        int r0 = row0 + warpM * 32 + mt * 16 + g;
        int r1 = r0 + 8;
        float be0 = (r0 < n) ? g_beta[r0] : 0.f;
        float be1 = (r1 < n) ? g_beta[r1] : 0.f;
#pragma unroll
        for (int nt = 0; nt < 8; nt++) {
            int col = n0 + nt * 8 + i2;
            float2 bv = *(const float2*)(bvec + col);
            if (r0 < n) {
                *(float2*)(out + (size_t)r0 * DIM + col) =
                    make_float2(c[mt][nt][0] + be0 * bv.x,
                                c[mt][nt][1] + be0 * bv.y);
            }
            if (r1 < n) {
                *(float2*)(out + (size_t)r1 * DIM + col) =
                    make_float2(c[mt][nt][2] + be1 * bv.x,
                                c[mt][nt][3] + be1 * bv.y);
            }
        }
    }
}

// ---------------------------------------------------------------------------
// Launch
// ---------------------------------------------------------------------------
extern "C" void kernel_launch(void* const* d_in, const int* in_sizes, int n_in,
                              void* d_out, int out_size) {
    const float* x   = (const float*)d_in[0];
    const int*   ei  = (const int*)d_in[1];
    const float* W   = (const float*)d_in[2];
    const float* b   = (const float*)d_in[3];
    float*       out = (float*)d_out;

    int n = in_sizes[0] / DIM;
    int e = in_sizes[1] / 2;

    size_t init_tot = (size_t)n * (DIM / 2);
    init_kernel<<<(int)((init_tot + 255) / 256), 256>>>(x, W, n);
    fill_kernel<<<(e + 255) / 256, 256>>>(ei, e, n);
    agg_kernel<<<((n * 32) + 255) / 256, 256>>>(n);
    gemm_mma_kernel<<<(n + TILE_M - 1) / TILE_M, 256>>>(b, out, n);
}